// round 13
// baseline (speedup 1.0000x reference)
#include <cuda_runtime.h>
#include <cuda_bf16.h>
#include <math.h>
#include <stdint.h>

#define T_STEPS 1024
#define NCTA 128
#define SPS 544   // sPart per-ksplit stride (floats): 32 rows * 17

// -------- packed fp32x2 helpers --------
__device__ __forceinline__ unsigned long long pack2(float x) {
    unsigned long long r; asm("mov.b64 %0, {%1, %1};" : "=l"(r) : "f"(x)); return r;
}
__device__ __forceinline__ void fma2(unsigned long long &d, unsigned long long a, unsigned long long b) {
    asm("fma.rn.f32x2 %0, %1, %2, %0;" : "+l"(d) : "l"(a), "l"(b));
}
__device__ __forceinline__ float2 unpack2(unsigned long long v) {
    float2 r; asm("mov.b64 {%0, %1}, %2;" : "=f"(r.x), "=f"(r.y) : "l"(v)); return r;
}

// -------- scratch (static device globals) --------
__device__ float g_xproj[(size_t)16384 * 4096];       // 256 MB
__device__ float g_hs[(size_t)16 * 1024 * 1024];      // 64 MB [b][t][h]
__device__ float g_hbuf[2][16384];                    // h double buffer [k][b]
__device__ int   g_flags[NCTA * 8];
__device__ unsigned int g_bar_count;
__device__ volatile unsigned int g_bar_gen;
__device__ __nv_bfloat16 g_A3[(size_t)16384 * 3072];  // 96 MB
__device__ __nv_bfloat16 g_W3[(size_t)4096 * 3072];   // 24 MB

// -------- software grid barrier (init only; replay-safe) --------
__device__ __forceinline__ void grid_barrier() {
    __syncthreads();
    if (threadIdx.x == 0) {
        __threadfence();
        unsigned int gen = g_bar_gen;
        unsigned int t = atomicAdd(&g_bar_count, 1u);
        if (t == NCTA - 1) {
            g_bar_count = 0u;
            __threadfence();
            g_bar_gen = gen + 1u;
        } else {
            while (g_bar_gen == gen) { }
            __threadfence();
        }
    }
    __syncthreads();
}

// -------- cp.async helpers --------
__device__ __forceinline__ uint32_t smem_u32(const void* p) {
    uint32_t a;
    asm("{ .reg .u64 t; cvta.to.shared.u64 t, %1; cvt.u32.u64 %0, t; }" : "=r"(a) : "l"(p));
    return a;
}
__device__ __forceinline__ void cp16(uint32_t dst, const void* src) {
    asm volatile("cp.async.cg.shared.global [%0], [%1], 16;" :: "r"(dst), "l"(src));
}
__device__ __forceinline__ void cp_commit() { asm volatile("cp.async.commit_group;"); }
template <int N>
__device__ __forceinline__ void cp_wait() { asm volatile("cp.async.wait_group %0;" :: "n"(N)); }

// -------- mma.sync bf16 --------
__device__ __forceinline__ void mma_bf16(float* c, const uint32_t* a, uint32_t b0, uint32_t b1) {
    asm volatile(
        "mma.sync.aligned.m16n8k16.row.col.f32.bf16.bf16.f32 "
        "{%0,%1,%2,%3}, {%4,%5,%6,%7}, {%8,%9}, {%0,%1,%2,%3};"
        : "+f"(c[0]), "+f"(c[1]), "+f"(c[2]), "+f"(c[3])
        : "r"(a[0]), "r"(a[1]), "r"(a[2]), "r"(a[3]), "r"(b0), "r"(b1));
}

// ===================================================================
// split3: fp32 [M][1024] -> bf16 [M][3072] split-concat (xproj prep)
// ===================================================================
__global__ __launch_bounds__(256) void split3(
    const float* __restrict__ src, __nv_bfloat16* __restrict__ dst,
    int off2, int off3, int seq_layout)
{
    size_t m = blockIdx.x;
    int k = threadIdx.x * 4;
    size_t si = seq_layout ? ((size_t)(m & 15) * 1048576 + (size_t)(m >> 4) * 1024 + k)
                           : (m * 1024 + k);
    float4 v = *(const float4*)(src + si);
    __nv_bfloat16 h0 = __float2bfloat16(v.x), h1 = __float2bfloat16(v.y);
    __nv_bfloat16 h2 = __float2bfloat16(v.z), h3 = __float2bfloat16(v.w);
    __nv_bfloat162 H0 = __halves2bfloat162(h0, h1), H1 = __halves2bfloat162(h2, h3);
    __nv_bfloat162 L0 = __halves2bfloat162(__float2bfloat16(v.x - __bfloat162float(h0)),
                                           __float2bfloat16(v.y - __bfloat162float(h1)));
    __nv_bfloat162 L1 = __halves2bfloat162(__float2bfloat16(v.z - __bfloat162float(h2)),
                                           __float2bfloat16(v.w - __bfloat162float(h3)));
    __nv_bfloat16* base = dst + m * 3072;
    *(__nv_bfloat162*)(base + k) = H0;          *(__nv_bfloat162*)(base + k + 2) = H1;
    *(__nv_bfloat162*)(base + off2 + k) = H0;   *(__nv_bfloat162*)(base + off2 + k + 2) = H1;
    *(__nv_bfloat162*)(base + off3 + k) = L0;   *(__nv_bfloat162*)(base + off3 + k + 2) = L1;
}

// ===================================================================
// Phase A HMMA GEMM, 4-stage cp.async pipeline (R11, known good)
// ===================================================================
#define BK 32
#define KIT 96
#define TILE_B 10240
__global__ __launch_bounds__(256, 2) void hmma_gemm(const float* __restrict__ bias, int bias_off)
{
    extern __shared__ __align__(16) char gsm[];
    __nv_bfloat16* As = (__nv_bfloat16*)gsm;
    __nv_bfloat16* Bs = (__nv_bfloat16*)(gsm + 4 * TILE_B);

    int tid = threadIdx.x;
    int n0 = blockIdx.x * 128, m0 = blockIdx.y * 128;
    int warp = tid >> 5, lane = tid & 31;
    int wm = (warp & 1) * 64, wn = (warp >> 1) * 32;
    int g = lane >> 2, q = lane & 3;

    int srow = tid >> 1;
    int scol = (tid & 1) * 16;
    const __nv_bfloat16* gA = g_A3 + (size_t)(m0 + srow) * 3072 + scol;
    const __nv_bfloat16* gB = g_W3 + (size_t)(n0 + srow) * 3072 + scol;
    uint32_t sOff = (srow * 40 + scol) * 2;
    uint32_t aBase = smem_u32(As), bBase = smem_u32(Bs);

    float acc[4][4][4];
#pragma unroll
    for (int i = 0; i < 4; i++)
#pragma unroll
        for (int j = 0; j < 4; j++)
#pragma unroll
            for (int r = 0; r < 4; r++) acc[i][j][r] = 0.f;

#pragma unroll
    for (int s = 0; s < 3; s++) {
        const __nv_bfloat16* a = gA + s * BK;
        const __nv_bfloat16* b = gB + s * BK;
        cp16(aBase + s * TILE_B + sOff, a);  cp16(aBase + s * TILE_B + sOff + 16, a + 8);
        cp16(bBase + s * TILE_B + sOff, b);  cp16(bBase + s * TILE_B + sOff + 16, b + 8);
        cp_commit();
    }

    for (int c = 0; c < KIT; c++) {
        cp_wait<2>();
        __syncthreads();

        if (c + 3 < KIT) {
            int s = (c + 3) & 3;
            const __nv_bfloat16* a = gA + (c + 3) * BK;
            const __nv_bfloat16* b = gB + (c + 3) * BK;
            cp16(aBase + s * TILE_B + sOff, a);  cp16(aBase + s * TILE_B + sOff + 16, a + 8);
            cp16(bBase + s * TILE_B + sOff, b);  cp16(bBase + s * TILE_B + sOff + 16, b + 8);
        }
        cp_commit();

        const __nv_bfloat16* Ab = As + (c & 3) * (TILE_B / 2);
        const __nv_bfloat16* Bb = Bs + (c & 3) * (TILE_B / 2);
#pragma unroll
        for (int kk = 0; kk < 32; kk += 16) {
            uint32_t af[4][4];
#pragma unroll
            for (int i = 0; i < 4; i++) {
                const __nv_bfloat16* p = Ab + (wm + i * 16 + g) * 40 + kk + 2 * q;
                af[i][0] = *(const uint32_t*)p;
                af[i][1] = *(const uint32_t*)(p + 8 * 40);
                af[i][2] = *(const uint32_t*)(p + 8);
                af[i][3] = *(const uint32_t*)(p + 8 * 40 + 8);
            }
#pragma unroll
            for (int j = 0; j < 4; j++) {
                const __nv_bfloat16* p = Bb + (wn + j * 8 + g) * 40 + kk + 2 * q;
                uint32_t b0 = *(const uint32_t*)p;
                uint32_t b1 = *(const uint32_t*)(p + 8);
#pragma unroll
                for (int i = 0; i < 4; i++)
                    mma_bf16(acc[i][j], af[i], b0, b1);
            }
        }
    }

#pragma unroll
    for (int j = 0; j < 4; j++) {
        int n = n0 + wn + j * 8 + 2 * q;
        float b0 = __ldg(bias + bias_off + n);
        float b1 = __ldg(bias + bias_off + n + 1);
#pragma unroll
        for (int i = 0; i < 4; i++) {
            int m = m0 + wm + i * 16 + g;
            float2 v0 = { acc[i][j][0] + b0, acc[i][j][1] + b1 };
            float2 v1 = { acc[i][j][2] + b0, acc[i][j][3] + b1 };
            *(float2*)(g_xproj + (size_t)m * 4096 + n) = v0;
            *(float2*)(g_xproj + (size_t)(m + 8) * 4096 + n) = v1;
        }
    }
}

// ===================================================================
// Phase B: persistent sLSTM recurrence, 512 threads (16 warps).
// warp = k-split (64 k); lane = gate row.
// R in SMEM transposed [k][row]: ONE conflict-free LDS.32 per k.
// -> ~90 free registers let ptxas software-pipeline the broadcast
//    h LDS.128 loads and hide their latency (vs. R-in-regs @126).
// h broadcast reads + per-warp private staging + flags as in R11.
// SMEM: sR 128K + sH 64K + sPart 34.8K = 231,424 B (1 CTA/SM).
// ===================================================================
__global__ __launch_bounds__(512, 1) void slstm_rec(const float* __restrict__ Rl)
{
    extern __shared__ float smem[];
    float* sR    = smem;                 // [1024][32]  k*32 + row
    float* sH    = smem + 32768;         // [1024][16]
    float* sPart = smem + 49152;         // [16][SPS]   ks*SPS + row*17 + b

    int tid = threadIdx.x;
    int ks = tid >> 5;          // warp id = 64-k split
    int lane = tid & 31;        // gate row
    int u_base = blockIdx.x * 8;

    if (tid == 0) g_flags[blockIdx.x * 8] = 0;
    grid_barrier();

    // ---- stage R transposed into smem (once): sR[k*32 + row] ----
    for (int idx = tid; idx < 8192; idx += 512) {
        int row = idx & 31;
        int k4 = idx >> 5;           // 0..255
        int grow = (row >> 3) * 1024 + u_base + (row & 7);
        float4 v = *(const float4*)(Rl + (size_t)grow * 1024 + k4 * 4);
        sR[(k4 * 4 + 0) * 32 + row] = v.x;
        sR[(k4 * 4 + 1) * 32 + row] = v.y;
        sR[(k4 * 4 + 2) * 32 + row] = v.z;
        sR[(k4 * 4 + 3) * 32 + row] = v.w;
    }
    // h0 = 0
    for (int i = tid; i < 16384; i += 512) sH[i] = 0.f;
    __syncthreads();

    // pointwise mapping (tid < 128): b = tid&15, u = tid>>4
    int pb = tid & 15, pu = tid >> 4;
    float creg = 0.f, nreg = 1.f, mreg = 0.f;

    const float* rk = sR + ks * 64 * 32 + lane;   // R[row=lane][k] walk
    const float* hk = sH + ks * 1024;
    float* pp = sPart + ks * SPS + lane * 17;
    const int* myflag = g_flags + (8 * ks + (lane & 7)) * 8;

    for (int t = 0; t < T_STEPS; t++) {
        // prefetch x_proj for this step
        float xpre[4];
        if (tid < 128) {
            const float* xp = g_xproj + ((size_t)t * 16 + pb) * 4096 + u_base + pu;
            xpre[0] = __ldg(xp);
            xpre[1] = __ldg(xp + 1024);
            xpre[2] = __ldg(xp + 2048);
            xpre[3] = __ldg(xp + 3072);
        }

        if (t > 0) {
            // wait for my 8 producers
            for (;;) {
                int f;
                asm volatile("ld.acquire.gpu.global.b32 %0, [%1];" : "=r"(f) : "l"(myflag));
                if (__all_sync(0xffffffffu, f >= t)) break;
            }
            // stage my 4KB h slice (warp-private)
            const float4* src4 = (const float4*)(g_hbuf[(t - 1) & 1]) + ks * 256 + lane;
            float4* dst4 = (float4*)sH + ks * 256 + lane;
#pragma unroll
            for (int j = 0; j < 8; j++) {
                float4 v;
                asm volatile("ld.global.cg.v4.f32 {%0,%1,%2,%3}, [%4];"
                             : "=f"(v.x), "=f"(v.y), "=f"(v.z), "=f"(v.w)
                             : "l"(src4 + j * 32));
                dst4[j * 32] = v;
            }
            __syncwarp();
        }

        // ---- GEMM: acc over my 64 k; R via 1 LDS.32/k, h broadcast ----
        unsigned long long acc[8];
#pragma unroll
        for (int j = 0; j < 8; j++) acc[j] = 0ull;

#pragma unroll
        for (int k = 0; k < 64; k++) {
            unsigned long long rp = pack2(rk[k * 32]);
            const unsigned long long* hp = (const unsigned long long*)(hk + k * 16);
            ulonglong2 h01 = *(const ulonglong2*)(hp + 0);
            ulonglong2 h23 = *(const ulonglong2*)(hp + 2);
            ulonglong2 h45 = *(const ulonglong2*)(hp + 4);
            ulonglong2 h67 = *(const ulonglong2*)(hp + 6);
            fma2(acc[0], rp, h01.x); fma2(acc[1], rp, h01.y);
            fma2(acc[2], rp, h23.x); fma2(acc[3], rp, h23.y);
            fma2(acc[4], rp, h45.x); fma2(acc[5], rp, h45.y);
            fma2(acc[6], rp, h67.x); fma2(acc[7], rp, h67.y);
        }

        // ---- store partials: 16 scalar STS, lane*17 -> conflict-free ----
        {
#pragma unroll
            for (int j = 0; j < 8; j++) {
                float2 v = unpack2(acc[j]);
                pp[j * 2] = v.x;
                pp[j * 2 + 1] = v.y;
            }
        }
        __syncthreads();   // BAR_A: all partials ready

        // ---- merged reduce + pointwise + publish (warps 0-3) ----
        if (tid < 128) {
            float pre[4];
#pragma unroll
            for (int g4 = 0; g4 < 4; g4++) {
                float s = xpre[g4];
                const float* qp = sPart + (g4 * 8 + pu) * 17 + pb;
#pragma unroll
                for (int k2 = 0; k2 < 16; k2++) s += qp[k2 * SPS];
                pre[g4] = s;
            }
            float ez = __expf(2.f * pre[0]);
            float z = __fdividef(ez - 1.f, ez + 1.f);
            float o = __fdividef(1.f, 1.f + __expf(-pre[3]));
            float mn = fmaxf(pre[2] + mreg, pre[1]);
            float ip = __expf(pre[1] - mn);
            float fp = __expf(pre[2] + mreg - mn);
            creg = fp * creg + ip * z;
            nreg = fp * nreg + ip;
            mreg = mn;
            float h = o * __fdividef(creg, nreg);
            g_hbuf[t & 1][(u_base + pu) * 16 + pb] = h;
            g_hs[(size_t)pb * 1048576 + (size_t)t * 1024 + u_base + pu] = h;
            asm volatile("bar.sync 1, 128;" ::: "memory");
            if (tid == 0) {
                __threadfence();
                g_flags[blockIdx.x * 8] = t + 1;
            }
        }
        __syncthreads();   // BAR_B: sPart consumed (single buffer WAR guard)
    }
}

// ===================================================================
// Final projection: h_last in g_hbuf[(T_STEPS-1)&1] = g_hbuf[1]
// ===================================================================
__global__ __launch_bounds__(256) void final_out(
    const float* __restrict__ Wout, const float* __restrict__ bout,
    float* __restrict__ out)
{
    const float* hsrc = g_hbuf[(T_STEPS - 1) & 1];
    int o = (blockIdx.x * blockDim.x + threadIdx.x) >> 5;
    int lane = threadIdx.x & 31;
    const float* wr = Wout + (size_t)o * 1024;
    float acc[16];
#pragma unroll
    for (int b = 0; b < 16; b++) acc[b] = 0.f;
    for (int k = lane; k < 1024; k += 32) {
        float w = wr[k];
        const float4* hp = (const float4*)(hsrc + k * 16);
        float4 h0 = hp[0], h1 = hp[1], h2 = hp[2], h3 = hp[3];
        acc[0]  += w * h0.x; acc[1]  += w * h0.y; acc[2]  += w * h0.z; acc[3]  += w * h0.w;
        acc[4]  += w * h1.x; acc[5]  += w * h1.y; acc[6]  += w * h1.z; acc[7]  += w * h1.w;
        acc[8]  += w * h2.x; acc[9]  += w * h2.y; acc[10] += w * h2.z; acc[11] += w * h2.w;
        acc[12] += w * h3.x; acc[13] += w * h3.y; acc[14] += w * h3.z; acc[15] += w * h3.w;
    }
#pragma unroll
    for (int b = 0; b < 16; b++) {
#pragma unroll
        for (int off = 16; off; off >>= 1)
            acc[b] += __shfl_down_sync(0xffffffffu, acc[b], off);
    }
    if (lane == 0) {
        float bo = bout[o];
#pragma unroll
        for (int b = 0; b < 16; b++)
            out[(size_t)b * 1024 + o] = acc[b] + bo;
    }
}

// ===================================================================
extern "C" void kernel_launch(void* const* d_in, const int* in_sizes, int n_in,
                              void* d_out, int out_size)
{
    const float* x    = (const float*)d_in[0];
    const float* W    = (const float*)d_in[1];
    const float* R    = (const float*)d_in[2];
    const float* bias = (const float*)d_in[3];
    const float* Wout = (const float*)d_in[4];
    const float* bout = (const float*)d_in[5];
    float* out = (float*)d_out;

    const int REC_SMEM = (32768 + 16384 + 16 * SPS) * 4;   // 231,424 B
    cudaFuncSetAttribute(slstm_rec, cudaFuncAttributeMaxDynamicSharedMemorySize, REC_SMEM);
    const int GEMM_SMEM = 8 * TILE_B;                       // 81,920 B
    cudaFuncSetAttribute(hmma_gemm, cudaFuncAttributeMaxDynamicSharedMemorySize, GEMM_SMEM);

    __nv_bfloat16 *ga3, *gw3;
    float *ghs;
    cudaGetSymbolAddress((void**)&ga3, g_A3);
    cudaGetSymbolAddress((void**)&gw3, g_W3);
    cudaGetSymbolAddress((void**)&ghs, g_hs);

    dim3 tgrid(32, 128);
    // ---- layer 0 ----
    split3<<<4096, 256>>>(W, gw3, 1024, 2048, 0);
    split3<<<16384, 256>>>(x, ga3, 2048, 1024, 1);
    hmma_gemm<<<tgrid, 256, GEMM_SMEM>>>(bias, 0);
    slstm_rec<<<NCTA, 512, REC_SMEM>>>(R);
    // ---- layer 1 ----
    split3<<<4096, 256>>>(W + (size_t)4096 * 1024, gw3, 1024, 2048, 0);
    split3<<<16384, 256>>>(ghs, ga3, 2048, 1024, 1);
    hmma_gemm<<<tgrid, 256, GEMM_SMEM>>>(bias, 4096);
    slstm_rec<<<NCTA, 512, REC_SMEM>>>(R + (size_t)4096 * 1024);
    // ---- output ----
    final_out<<<128, 256>>>(Wout, bout, out);
}

// round 15
// speedup vs baseline: 1.0673x; 1.0673x over previous
#include <cuda_runtime.h>
#include <cuda_bf16.h>
#include <math.h>
#include <stdint.h>

#define T_STEPS 1024
#define NCTA 128
#define PS 584   // sPart per-ksplit stride (floats): 32 rows * 18 + 8 pad

// -------- packed fp32x2 helpers --------
__device__ __forceinline__ unsigned long long pack2(float x) {
    unsigned long long r; asm("mov.b64 %0, {%1, %1};" : "=l"(r) : "f"(x)); return r;
}
__device__ __forceinline__ void fma2(unsigned long long &d, unsigned long long a, unsigned long long b) {
    asm("fma.rn.f32x2 %0, %1, %2, %0;" : "+l"(d) : "l"(a), "l"(b));
}

// -------- scratch (static device globals) --------
__device__ float g_xproj[(size_t)16384 * 4096];       // 256 MB
__device__ float g_hs[(size_t)16 * 1024 * 1024];      // 64 MB [b][t][h]
__device__ float g_hbuf[2][16384];                    // h double buffer [k][b]
__device__ int   g_flags[NCTA * 8];
__device__ unsigned int g_bar_count;
__device__ volatile unsigned int g_bar_gen;
__device__ __nv_bfloat16 g_A3[(size_t)16384 * 3072];  // 96 MB
__device__ __nv_bfloat16 g_W3[(size_t)4096 * 3072];   // 24 MB

// -------- software grid barrier (init only; replay-safe) --------
__device__ __forceinline__ void grid_barrier() {
    __syncthreads();
    if (threadIdx.x == 0) {
        __threadfence();
        unsigned int gen = g_bar_gen;
        unsigned int t = atomicAdd(&g_bar_count, 1u);
        if (t == NCTA - 1) {
            g_bar_count = 0u;
            __threadfence();
            g_bar_gen = gen + 1u;
        } else {
            while (g_bar_gen == gen) { }
            __threadfence();
        }
    }
    __syncthreads();
}

// -------- cp.async helpers --------
__device__ __forceinline__ uint32_t smem_u32(const void* p) {
    uint32_t a;
    asm("{ .reg .u64 t; cvta.to.shared.u64 t, %1; cvt.u32.u64 %0, t; }" : "=r"(a) : "l"(p));
    return a;
}
__device__ __forceinline__ void cp16(uint32_t dst, const void* src) {
    asm volatile("cp.async.cg.shared.global [%0], [%1], 16;" :: "r"(dst), "l"(src));
}
__device__ __forceinline__ void cp_commit() { asm volatile("cp.async.commit_group;"); }
template <int N>
__device__ __forceinline__ void cp_wait() { asm volatile("cp.async.wait_group %0;" :: "n"(N)); }

// -------- mma.sync bf16 --------
__device__ __forceinline__ void mma_bf16(float* c, const uint32_t* a, uint32_t b0, uint32_t b1) {
    asm volatile(
        "mma.sync.aligned.m16n8k16.row.col.f32.bf16.bf16.f32 "
        "{%0,%1,%2,%3}, {%4,%5,%6,%7}, {%8,%9}, {%0,%1,%2,%3};"
        : "+f"(c[0]), "+f"(c[1]), "+f"(c[2]), "+f"(c[3])
        : "r"(a[0]), "r"(a[1]), "r"(a[2]), "r"(a[3]), "r"(b0), "r"(b1));
}

// ===================================================================
// split3: fp32 [M][1024] -> bf16 [M][3072] split-concat (xproj prep)
// ===================================================================
__global__ __launch_bounds__(256) void split3(
    const float* __restrict__ src, __nv_bfloat16* __restrict__ dst,
    int off2, int off3, int seq_layout)
{
    size_t m = blockIdx.x;
    int k = threadIdx.x * 4;
    size_t si = seq_layout ? ((size_t)(m & 15) * 1048576 + (size_t)(m >> 4) * 1024 + k)
                           : (m * 1024 + k);
    float4 v = *(const float4*)(src + si);
    __nv_bfloat16 h0 = __float2bfloat16(v.x), h1 = __float2bfloat16(v.y);
    __nv_bfloat16 h2 = __float2bfloat16(v.z), h3 = __float2bfloat16(v.w);
    __nv_bfloat162 H0 = __halves2bfloat162(h0, h1), H1 = __halves2bfloat162(h2, h3);
    __nv_bfloat162 L0 = __halves2bfloat162(__float2bfloat16(v.x - __bfloat162float(h0)),
                                           __float2bfloat16(v.y - __bfloat162float(h1)));
    __nv_bfloat162 L1 = __halves2bfloat162(__float2bfloat16(v.z - __bfloat162float(h2)),
                                           __float2bfloat16(v.w - __bfloat162float(h3)));
    __nv_bfloat16* base = dst + m * 3072;
    *(__nv_bfloat162*)(base + k) = H0;          *(__nv_bfloat162*)(base + k + 2) = H1;
    *(__nv_bfloat162*)(base + off2 + k) = H0;   *(__nv_bfloat162*)(base + off2 + k + 2) = H1;
    *(__nv_bfloat162*)(base + off3 + k) = L0;   *(__nv_bfloat162*)(base + off3 + k + 2) = L1;
}

// ===================================================================
// Phase A HMMA GEMM, 4-stage cp.async pipeline (R11, known good)
// ===================================================================
#define BK 32
#define KIT 96
#define TILE_B 10240
__global__ __launch_bounds__(256, 2) void hmma_gemm(const float* __restrict__ bias, int bias_off)
{
    extern __shared__ __align__(16) char gsm[];
    __nv_bfloat16* As = (__nv_bfloat16*)gsm;
    __nv_bfloat16* Bs = (__nv_bfloat16*)(gsm + 4 * TILE_B);

    int tid = threadIdx.x;
    int n0 = blockIdx.x * 128, m0 = blockIdx.y * 128;
    int warp = tid >> 5, lane = tid & 31;
    int wm = (warp & 1) * 64, wn = (warp >> 1) * 32;
    int g = lane >> 2, q = lane & 3;

    int srow = tid >> 1;
    int scol = (tid & 1) * 16;
    const __nv_bfloat16* gA = g_A3 + (size_t)(m0 + srow) * 3072 + scol;
    const __nv_bfloat16* gB = g_W3 + (size_t)(n0 + srow) * 3072 + scol;
    uint32_t sOff = (srow * 40 + scol) * 2;
    uint32_t aBase = smem_u32(As), bBase = smem_u32(Bs);

    float acc[4][4][4];
#pragma unroll
    for (int i = 0; i < 4; i++)
#pragma unroll
        for (int j = 0; j < 4; j++)
#pragma unroll
            for (int r = 0; r < 4; r++) acc[i][j][r] = 0.f;

#pragma unroll
    for (int s = 0; s < 3; s++) {
        const __nv_bfloat16* a = gA + s * BK;
        const __nv_bfloat16* b = gB + s * BK;
        cp16(aBase + s * TILE_B + sOff, a);  cp16(aBase + s * TILE_B + sOff + 16, a + 8);
        cp16(bBase + s * TILE_B + sOff, b);  cp16(bBase + s * TILE_B + sOff + 16, b + 8);
        cp_commit();
    }

    for (int c = 0; c < KIT; c++) {
        cp_wait<2>();
        __syncthreads();

        if (c + 3 < KIT) {
            int s = (c + 3) & 3;
            const __nv_bfloat16* a = gA + (c + 3) * BK;
            const __nv_bfloat16* b = gB + (c + 3) * BK;
            cp16(aBase + s * TILE_B + sOff, a);  cp16(aBase + s * TILE_B + sOff + 16, a + 8);
            cp16(bBase + s * TILE_B + sOff, b);  cp16(bBase + s * TILE_B + sOff + 16, b + 8);
        }
        cp_commit();

        const __nv_bfloat16* Ab = As + (c & 3) * (TILE_B / 2);
        const __nv_bfloat16* Bb = Bs + (c & 3) * (TILE_B / 2);
#pragma unroll
        for (int kk = 0; kk < 32; kk += 16) {
            uint32_t af[4][4];
#pragma unroll
            for (int i = 0; i < 4; i++) {
                const __nv_bfloat16* p = Ab + (wm + i * 16 + g) * 40 + kk + 2 * q;
                af[i][0] = *(const uint32_t*)p;
                af[i][1] = *(const uint32_t*)(p + 8 * 40);
                af[i][2] = *(const uint32_t*)(p + 8);
                af[i][3] = *(const uint32_t*)(p + 8 * 40 + 8);
            }
#pragma unroll
            for (int j = 0; j < 4; j++) {
                const __nv_bfloat16* p = Bb + (wn + j * 8 + g) * 40 + kk + 2 * q;
                uint32_t b0 = *(const uint32_t*)p;
                uint32_t b1 = *(const uint32_t*)(p + 8);
#pragma unroll
                for (int i = 0; i < 4; i++)
                    mma_bf16(acc[i][j], af[i], b0, b1);
            }
        }
    }

#pragma unroll
    for (int j = 0; j < 4; j++) {
        int n = n0 + wn + j * 8 + 2 * q;
        float b0 = __ldg(bias + bias_off + n);
        float b1 = __ldg(bias + bias_off + n + 1);
#pragma unroll
        for (int i = 0; i < 4; i++) {
            int m = m0 + wm + i * 16 + g;
            float2 v0 = { acc[i][j][0] + b0, acc[i][j][1] + b1 };
            float2 v1 = { acc[i][j][2] + b0, acc[i][j][3] + b1 };
            *(float2*)(g_xproj + (size_t)m * 4096 + n) = v0;
            *(float2*)(g_xproj + (size_t)(m + 8) * 4096 + n) = v1;
        }
    }
}

// ===================================================================
// Phase B: persistent sLSTM recurrence, 1024 threads (32 warps).
// warp = 32-k slice (ks 0..31); lane = gate row.
// R split: k[0..15] in REGISTERS (16/thread), k[16..31] in SMEM
// transposed (lane-stride-1, conflict-free).  regs ~55 (<64 cap).
// 8 warps/SMSP hide LDS/L2 latency. h reads broadcast LDS.128.
// Partials: STS.64 at lane*18 (even -> 8B aligned; fixes R14 fault).
// SMEM: sR 64K + sH 64K + sPart 32*PS*4=74.75K = 205,824 B.
// ===================================================================
__global__ __launch_bounds__(1024, 1) void slstm_rec(const float* __restrict__ Rl)
{
    extern __shared__ float smem[];
    float* sR    = smem;                  // [512][32]: (ks*16+kk)*32 + lane
    float* sH    = smem + 16384;          // [1024][16]
    float* sPart = smem + 32768;          // [32][PS]: ks*PS + row*18 + b

    int tid = threadIdx.x;
    int ks = tid >> 5;          // warp id = 32-k slice
    int lane = tid & 31;        // gate row
    int u_base = blockIdx.x * 8;

    if (tid == 0) g_flags[blockIdx.x * 8] = 0;
    grid_barrier();

    // ---- R slice: first 16 k -> regs, last 16 k -> sR ----
    int grow = (lane >> 3) * 1024 + u_base + (lane & 7);
    const float* rrow = Rl + (size_t)grow * 1024 + ks * 32;
    float Rreg[16];
#pragma unroll
    for (int j = 0; j < 16; j += 4) {
        float4 v = *(const float4*)(rrow + j);
        Rreg[j] = v.x; Rreg[j + 1] = v.y; Rreg[j + 2] = v.z; Rreg[j + 3] = v.w;
    }
#pragma unroll
    for (int j = 0; j < 16; j += 4) {
        float4 v = *(const float4*)(rrow + 16 + j);
        sR[(ks * 16 + j + 0) * 32 + lane] = v.x;
        sR[(ks * 16 + j + 1) * 32 + lane] = v.y;
        sR[(ks * 16 + j + 2) * 32 + lane] = v.z;
        sR[(ks * 16 + j + 3) * 32 + lane] = v.w;
    }
    // h0 = 0
    for (int i = tid; i < 16384; i += 1024) sH[i] = 0.f;
    __syncthreads();

    // pointwise mapping (tid < 128): b = tid&15, u = tid>>4
    int pb = tid & 15, pu = tid >> 4;
    float creg = 0.f, nreg = 1.f, mreg = 0.f;

    const float* hk = sH + ks * 512;              // my 32 k x 16 b
    const float* rs = sR + ks * 16 * 32 + lane;   // smem half of R
    float* pp = sPart + ks * PS + lane * 18;      // even stride: STS.64 OK
    const int* myflag = g_flags + (4 * ks + (lane & 3)) * 8;   // 4 producers

    for (int t = 0; t < T_STEPS; t++) {
        // prefetch x_proj for this step
        float xpre[4];
        if (tid < 128) {
            const float* xp = g_xproj + ((size_t)t * 16 + pb) * 4096 + u_base + pu;
            xpre[0] = __ldg(xp);
            xpre[1] = __ldg(xp + 1024);
            xpre[2] = __ldg(xp + 2048);
            xpre[3] = __ldg(xp + 3072);
        }

        if (t > 0) {
            // wait for my 4 producers
            for (;;) {
                int f;
                asm volatile("ld.acquire.gpu.global.b32 %0, [%1];" : "=r"(f) : "l"(myflag));
                if (__all_sync(0xffffffffu, f >= t)) break;
            }
            // stage my 2KB h slice (warp-private): 128 float4, 4/lane
            const float4* src4 = (const float4*)(g_hbuf[(t - 1) & 1]) + ks * 128 + lane;
            float4* dst4 = (float4*)sH + ks * 128 + lane;
#pragma unroll
            for (int j = 0; j < 4; j++) {
                float4 v;
                asm volatile("ld.global.cg.v4.f32 {%0,%1,%2,%3}, [%4];"
                             : "=f"(v.x), "=f"(v.y), "=f"(v.z), "=f"(v.w)
                             : "l"(src4 + j * 32));
                dst4[j * 32] = v;
            }
            __syncwarp();
        }

        // ---- GEMM: 32 k; first 16 with reg-R, last 16 with smem-R ----
        unsigned long long acc[8];
#pragma unroll
        for (int j = 0; j < 8; j++) acc[j] = 0ull;

#pragma unroll
        for (int k = 0; k < 16; k++) {
            unsigned long long rp = pack2(Rreg[k]);
            const unsigned long long* hp = (const unsigned long long*)(hk + k * 16);
            ulonglong2 h01 = *(const ulonglong2*)(hp + 0);
            ulonglong2 h23 = *(const ulonglong2*)(hp + 2);
            ulonglong2 h45 = *(const ulonglong2*)(hp + 4);
            ulonglong2 h67 = *(const ulonglong2*)(hp + 6);
            fma2(acc[0], rp, h01.x); fma2(acc[1], rp, h01.y);
            fma2(acc[2], rp, h23.x); fma2(acc[3], rp, h23.y);
            fma2(acc[4], rp, h45.x); fma2(acc[5], rp, h45.y);
            fma2(acc[6], rp, h67.x); fma2(acc[7], rp, h67.y);
        }
#pragma unroll
        for (int k = 0; k < 16; k++) {
            unsigned long long rp = pack2(rs[k * 32]);
            const unsigned long long* hp = (const unsigned long long*)(hk + (16 + k) * 16);
            ulonglong2 h01 = *(const ulonglong2*)(hp + 0);
            ulonglong2 h23 = *(const ulonglong2*)(hp + 2);
            ulonglong2 h45 = *(const ulonglong2*)(hp + 4);
            ulonglong2 h67 = *(const ulonglong2*)(hp + 6);
            fma2(acc[0], rp, h01.x); fma2(acc[1], rp, h01.y);
            fma2(acc[2], rp, h23.x); fma2(acc[3], rp, h23.y);
            fma2(acc[4], rp, h45.x); fma2(acc[5], rp, h45.y);
            fma2(acc[6], rp, h67.x); fma2(acc[7], rp, h67.y);
        }

        // ---- partials: 8 STS.64 at even stride-18 rows ----
#pragma unroll
        for (int j = 0; j < 8; j++)
            *(unsigned long long*)(pp + j * 2) = acc[j];
        __syncthreads();   // BAR_A: all partials ready

        // ---- merged reduce + pointwise + publish (warps 0-3) ----
        if (tid < 128) {
            float pre[4];
#pragma unroll
            for (int g4 = 0; g4 < 4; g4++) {
                const float* qp = sPart + (g4 * 8 + pu) * 18 + pb;
                float s0 = xpre[g4], s1 = 0.f;
#pragma unroll
                for (int k2 = 0; k2 < 32; k2 += 2) {
                    s0 += qp[k2 * PS];
                    s1 += qp[(k2 + 1) * PS];
                }
                pre[g4] = s0 + s1;
            }
            float ez = __expf(2.f * pre[0]);
            float z = __fdividef(ez - 1.f, ez + 1.f);
            float o = __fdividef(1.f, 1.f + __expf(-pre[3]));
            float mn = fmaxf(pre[2] + mreg, pre[1]);
            float ip = __expf(pre[1] - mn);
            float fp = __expf(pre[2] + mreg - mn);
            creg = fp * creg + ip * z;
            nreg = fp * nreg + ip;
            mreg = mn;
            float h = o * __fdividef(creg, nreg);
            g_hbuf[t & 1][(u_base + pu) * 16 + pb] = h;
            g_hs[(size_t)pb * 1048576 + (size_t)t * 1024 + u_base + pu] = h;
            asm volatile("bar.sync 1, 128;" ::: "memory");
            if (tid == 0) {
                __threadfence();
                g_flags[blockIdx.x * 8] = t + 1;
            }
        }
        __syncthreads();   // BAR_B: sPart consumed (single-buffer WAR guard)
    }
}

// ===================================================================
// Final projection: h_last in g_hbuf[(T_STEPS-1)&1] = g_hbuf[1]
// ===================================================================
__global__ __launch_bounds__(256) void final_out(
    const float* __restrict__ Wout, const float* __restrict__ bout,
    float* __restrict__ out)
{
    const float* hsrc = g_hbuf[(T_STEPS - 1) & 1];
    int o = (blockIdx.x * blockDim.x + threadIdx.x) >> 5;
    int lane = threadIdx.x & 31;
    const float* wr = Wout + (size_t)o * 1024;
    float acc[16];
#pragma unroll
    for (int b = 0; b < 16; b++) acc[b] = 0.f;
    for (int k = lane; k < 1024; k += 32) {
        float w = wr[k];
        const float4* hp = (const float4*)(hsrc + k * 16);
        float4 h0 = hp[0], h1 = hp[1], h2 = hp[2], h3 = hp[3];
        acc[0]  += w * h0.x; acc[1]  += w * h0.y; acc[2]  += w * h0.z; acc[3]  += w * h0.w;
        acc[4]  += w * h1.x; acc[5]  += w * h1.y; acc[6]  += w * h1.z; acc[7]  += w * h1.w;
        acc[8]  += w * h2.x; acc[9]  += w * h2.y; acc[10] += w * h2.z; acc[11] += w * h2.w;
        acc[12] += w * h3.x; acc[13] += w * h3.y; acc[14] += w * h3.z; acc[15] += w * h3.w;
    }
#pragma unroll
    for (int b = 0; b < 16; b++) {
#pragma unroll
        for (int off = 16; off; off >>= 1)
            acc[b] += __shfl_down_sync(0xffffffffu, acc[b], off);
    }
    if (lane == 0) {
        float bo = bout[o];
#pragma unroll
        for (int b = 0; b < 16; b++)
            out[(size_t)b * 1024 + o] = acc[b] + bo;
    }
}

// ===================================================================
extern "C" void kernel_launch(void* const* d_in, const int* in_sizes, int n_in,
                              void* d_out, int out_size)
{
    const float* x    = (const float*)d_in[0];
    const float* W    = (const float*)d_in[1];
    const float* R    = (const float*)d_in[2];
    const float* bias = (const float*)d_in[3];
    const float* Wout = (const float*)d_in[4];
    const float* bout = (const float*)d_in[5];
    float* out = (float*)d_out;

    const int REC_SMEM = (16384 + 16384 + 32 * PS) * 4;    // 205,824 B
    cudaFuncSetAttribute(slstm_rec, cudaFuncAttributeMaxDynamicSharedMemorySize, REC_SMEM);
    const int GEMM_SMEM = 8 * TILE_B;                       // 81,920 B
    cudaFuncSetAttribute(hmma_gemm, cudaFuncAttributeMaxDynamicSharedMemorySize, GEMM_SMEM);

    __nv_bfloat16 *ga3, *gw3;
    float *ghs;
    cudaGetSymbolAddress((void**)&ga3, g_A3);
    cudaGetSymbolAddress((void**)&gw3, g_W3);
    cudaGetSymbolAddress((void**)&ghs, g_hs);

    dim3 tgrid(32, 128);
    // ---- layer 0 ----
    split3<<<4096, 256>>>(W, gw3, 1024, 2048, 0);
    split3<<<16384, 256>>>(x, ga3, 2048, 1024, 1);
    hmma_gemm<<<tgrid, 256, GEMM_SMEM>>>(bias, 0);
    slstm_rec<<<NCTA, 1024, REC_SMEM>>>(R);
    // ---- layer 1 ----
    split3<<<4096, 256>>>(W + (size_t)4096 * 1024, gw3, 1024, 2048, 0);
    split3<<<16384, 256>>>(ghs, ga3, 2048, 1024, 1);
    hmma_gemm<<<tgrid, 256, GEMM_SMEM>>>(bias, 4096);
    slstm_rec<<<NCTA, 1024, REC_SMEM>>>(R + (size_t)4096 * 1024);
    // ---- output ----
    final_out<<<128, 256>>>(Wout, bout, out);
}

// round 16
// speedup vs baseline: 1.0772x; 1.0093x over previous
#include <cuda_runtime.h>
#include <cuda_bf16.h>
#include <math.h>
#include <stdint.h>

#define T_STEPS 1024
#define NCTA 128
#define PS 584   // sPart per-ksplit stride (floats)

// -------- packed fp32x2 helpers --------
__device__ __forceinline__ unsigned long long pack2(float x) {
    unsigned long long r; asm("mov.b64 %0, {%1, %1};" : "=l"(r) : "f"(x)); return r;
}
__device__ __forceinline__ void fma2(unsigned long long &d, unsigned long long a, unsigned long long b) {
    asm("fma.rn.f32x2 %0, %1, %2, %0;" : "+l"(d) : "l"(a), "l"(b));
}

// -------- scratch (static device globals) --------
__device__ float g_xproj[(size_t)16384 * 4096];       // 256 MB
__device__ float g_hbuf[2][16384];                    // h double buffer [k][b]
__device__ int   g_flags[NCTA * 8];
__device__ unsigned int g_bar_count;
__device__ volatile unsigned int g_bar_gen;
__device__ __nv_bfloat16 g_A3[(size_t)16384 * 3072];  // 96 MB [m][Ah|Al|Ah]
__device__ __nv_bfloat16 g_W3[(size_t)4096 * 3072];   // 24 MB [n][Wh|Wh|Wl]

// -------- software grid barrier (init only; replay-safe) --------
__device__ __forceinline__ void grid_barrier() {
    __syncthreads();
    if (threadIdx.x == 0) {
        __threadfence();
        unsigned int gen = g_bar_gen;
        unsigned int t = atomicAdd(&g_bar_count, 1u);
        if (t == NCTA - 1) {
            g_bar_count = 0u;
            __threadfence();
            g_bar_gen = gen + 1u;
        } else {
            while (g_bar_gen == gen) { }
            __threadfence();
        }
    }
    __syncthreads();
}

// -------- cp.async helpers --------
__device__ __forceinline__ uint32_t smem_u32(const void* p) {
    uint32_t a;
    asm("{ .reg .u64 t; cvta.to.shared.u64 t, %1; cvt.u32.u64 %0, t; }" : "=r"(a) : "l"(p));
    return a;
}
__device__ __forceinline__ void cp16(uint32_t dst, const void* src) {
    asm volatile("cp.async.cg.shared.global [%0], [%1], 16;" :: "r"(dst), "l"(src));
}
__device__ __forceinline__ void cp_commit() { asm volatile("cp.async.commit_group;"); }
template <int N>
__device__ __forceinline__ void cp_wait() { asm volatile("cp.async.wait_group %0;" :: "n"(N)); }

// -------- mma.sync bf16 --------
__device__ __forceinline__ void mma_bf16(float* c, const uint32_t* a, uint32_t b0, uint32_t b1) {
    asm volatile(
        "mma.sync.aligned.m16n8k16.row.col.f32.bf16.bf16.f32 "
        "{%0,%1,%2,%3}, {%4,%5,%6,%7}, {%8,%9}, {%0,%1,%2,%3};"
        : "+f"(c[0]), "+f"(c[1]), "+f"(c[2]), "+f"(c[3])
        : "r"(a[0]), "r"(a[1]), "r"(a[2]), "r"(a[3]), "r"(b0), "r"(b1));
}

// ===================================================================
// split3: fp32 [M][1024] -> bf16 [M][3072] split-concat
//   (used for W both layers, and layer-0 input x)
// ===================================================================
__global__ __launch_bounds__(256) void split3(
    const float* __restrict__ src, __nv_bfloat16* __restrict__ dst,
    int off2, int off3, int seq_layout)
{
    size_t m = blockIdx.x;
    int k = threadIdx.x * 4;
    size_t si = seq_layout ? ((size_t)(m & 15) * 1048576 + (size_t)(m >> 4) * 1024 + k)
                           : (m * 1024 + k);
    float4 v = *(const float4*)(src + si);
    __nv_bfloat16 h0 = __float2bfloat16(v.x), h1 = __float2bfloat16(v.y);
    __nv_bfloat16 h2 = __float2bfloat16(v.z), h3 = __float2bfloat16(v.w);
    __nv_bfloat162 H0 = __halves2bfloat162(h0, h1), H1 = __halves2bfloat162(h2, h3);
    __nv_bfloat162 L0 = __halves2bfloat162(__float2bfloat16(v.x - __bfloat162float(h0)),
                                           __float2bfloat16(v.y - __bfloat162float(h1)));
    __nv_bfloat162 L1 = __halves2bfloat162(__float2bfloat16(v.z - __bfloat162float(h2)),
                                           __float2bfloat16(v.w - __bfloat162float(h3)));
    __nv_bfloat16* base = dst + m * 3072;
    *(__nv_bfloat162*)(base + k) = H0;          *(__nv_bfloat162*)(base + k + 2) = H1;
    *(__nv_bfloat162*)(base + off2 + k) = H0;   *(__nv_bfloat162*)(base + off2 + k + 2) = H1;
    *(__nv_bfloat162*)(base + off3 + k) = L0;   *(__nv_bfloat162*)(base + off3 + k + 2) = L1;
}

// ===================================================================
// Phase A HMMA GEMM, 4-stage cp.async pipeline (R11, known good)
// ===================================================================
#define BK 32
#define KIT 96
#define TILE_B 10240
__global__ __launch_bounds__(256, 2) void hmma_gemm(const float* __restrict__ bias, int bias_off)
{
    extern __shared__ __align__(16) char gsm[];
    __nv_bfloat16* As = (__nv_bfloat16*)gsm;
    __nv_bfloat16* Bs = (__nv_bfloat16*)(gsm + 4 * TILE_B);

    int tid = threadIdx.x;
    int n0 = blockIdx.x * 128, m0 = blockIdx.y * 128;
    int warp = tid >> 5, lane = tid & 31;
    int wm = (warp & 1) * 64, wn = (warp >> 1) * 32;
    int g = lane >> 2, q = lane & 3;

    int srow = tid >> 1;
    int scol = (tid & 1) * 16;
    const __nv_bfloat16* gA = g_A3 + (size_t)(m0 + srow) * 3072 + scol;
    const __nv_bfloat16* gB = g_W3 + (size_t)(n0 + srow) * 3072 + scol;
    uint32_t sOff = (srow * 40 + scol) * 2;
    uint32_t aBase = smem_u32(As), bBase = smem_u32(Bs);

    float acc[4][4][4];
#pragma unroll
    for (int i = 0; i < 4; i++)
#pragma unroll
        for (int j = 0; j < 4; j++)
#pragma unroll
            for (int r = 0; r < 4; r++) acc[i][j][r] = 0.f;

#pragma unroll
    for (int s = 0; s < 3; s++) {
        const __nv_bfloat16* a = gA + s * BK;
        const __nv_bfloat16* b = gB + s * BK;
        cp16(aBase + s * TILE_B + sOff, a);  cp16(aBase + s * TILE_B + sOff + 16, a + 8);
        cp16(bBase + s * TILE_B + sOff, b);  cp16(bBase + s * TILE_B + sOff + 16, b + 8);
        cp_commit();
    }

    for (int c = 0; c < KIT; c++) {
        cp_wait<2>();
        __syncthreads();

        if (c + 3 < KIT) {
            int s = (c + 3) & 3;
            const __nv_bfloat16* a = gA + (c + 3) * BK;
            const __nv_bfloat16* b = gB + (c + 3) * BK;
            cp16(aBase + s * TILE_B + sOff, a);  cp16(aBase + s * TILE_B + sOff + 16, a + 8);
            cp16(bBase + s * TILE_B + sOff, b);  cp16(bBase + s * TILE_B + sOff + 16, b + 8);
        }
        cp_commit();

        const __nv_bfloat16* Ab = As + (c & 3) * (TILE_B / 2);
        const __nv_bfloat16* Bb = Bs + (c & 3) * (TILE_B / 2);
#pragma unroll
        for (int kk = 0; kk < 32; kk += 16) {
            uint32_t af[4][4];
#pragma unroll
            for (int i = 0; i < 4; i++) {
                const __nv_bfloat16* p = Ab + (wm + i * 16 + g) * 40 + kk + 2 * q;
                af[i][0] = *(const uint32_t*)p;
                af[i][1] = *(const uint32_t*)(p + 8 * 40);
                af[i][2] = *(const uint32_t*)(p + 8);
                af[i][3] = *(const uint32_t*)(p + 8 * 40 + 8);
            }
#pragma unroll
            for (int j = 0; j < 4; j++) {
                const __nv_bfloat16* p = Bb + (wn + j * 8 + g) * 40 + kk + 2 * q;
                uint32_t b0 = *(const uint32_t*)p;
                uint32_t b1 = *(const uint32_t*)(p + 8);
#pragma unroll
                for (int i = 0; i < 4; i++)
                    mma_bf16(acc[i][j], af[i], b0, b1);
            }
        }
    }

#pragma unroll
    for (int j = 0; j < 4; j++) {
        int n = n0 + wn + j * 8 + 2 * q;
        float b0 = __ldg(bias + bias_off + n);
        float b1 = __ldg(bias + bias_off + n + 1);
#pragma unroll
        for (int i = 0; i < 4; i++) {
            int m = m0 + wm + i * 16 + g;
            float2 v0 = { acc[i][j][0] + b0, acc[i][j][1] + b1 };
            float2 v1 = { acc[i][j][2] + b0, acc[i][j][3] + b1 };
            *(float2*)(g_xproj + (size_t)m * 4096 + n) = v0;
            *(float2*)(g_xproj + (size_t)(m + 8) * 4096 + n) = v1;
        }
    }
}

// ===================================================================
// Phase B: persistent sLSTM recurrence — exact R11 core (6.36us/step):
// 512 threads; warp = 64-k split; lane = gate row; R in registers;
// double-buffered partials (no BAR_B); merged reduce+pointwise.
// Changes vs R11: relaxed polling + acquire fence; layer-0 writes the
// layer-1 bf16 split operand (g_A3) directly; g_hs eliminated.
// ===================================================================
__global__ __launch_bounds__(512, 1) void slstm_rec(const float* __restrict__ Rl, int write_a3)
{
    extern __shared__ float smem[];
    float* sH    = smem;                 // [1024][16]
    float* sPart = smem + 16384;         // [2][16][PS]

    int tid = threadIdx.x;
    int ks = tid >> 5;
    int lane = tid & 31;
    int u_base = blockIdx.x * 8;

    if (tid == 0) g_flags[blockIdx.x * 8] = 0;
    grid_barrier();

    int grow = (lane >> 3) * 1024 + u_base + (lane & 7);
    const float* rrow = Rl + (size_t)grow * 1024 + ks * 64;
    float Rreg[64];
#pragma unroll
    for (int j = 0; j < 64; j += 4) {
        float4 v = *(const float4*)(rrow + j);
        Rreg[j] = v.x; Rreg[j + 1] = v.y; Rreg[j + 2] = v.z; Rreg[j + 3] = v.w;
    }

    for (int i = tid; i < 16384; i += 512) sH[i] = 0.f;
    __syncthreads();

    // pointwise mapping (tid < 128): b = tid&15, u = tid>>4
    int pb = tid & 15, pu = tid >> 4;
    float creg = 0.f, nreg = 1.f, mreg = 0.f;

    const float* hk = sH + ks * 1024;
    float* pprow0 = sPart + ks * PS + lane * 18;
    const int* myflag = g_flags + (8 * ks + (lane & 7)) * 8;

    for (int t = 0; t < T_STEPS; t++) {
        int pbuf = (t & 1) * (16 * PS);

        float xpre[4];
        if (tid < 128) {
            const float* xp = g_xproj + ((size_t)t * 16 + pb) * 4096 + u_base + pu;
            xpre[0] = __ldg(xp);
            xpre[1] = __ldg(xp + 1024);
            xpre[2] = __ldg(xp + 2048);
            xpre[3] = __ldg(xp + 3072);
        }

        if (t > 0) {
            // relaxed poll, then one acquire fence (pairs with producer's
            // __threadfence release before the flag store)
            for (;;) {
                int f;
                asm volatile("ld.relaxed.gpu.global.b32 %0, [%1];" : "=r"(f) : "l"(myflag));
                if (__all_sync(0xffffffffu, f >= t)) break;
            }
            asm volatile("fence.acq_rel.gpu;" ::: "memory");
            const float4* src4 = (const float4*)(g_hbuf[(t - 1) & 1]) + ks * 256 + lane;
            float4* dst4 = (float4*)sH + ks * 256 + lane;
#pragma unroll
            for (int j = 0; j < 8; j++) {
                float4 v;
                asm volatile("ld.global.cg.v4.f32 {%0,%1,%2,%3}, [%4];"
                             : "=f"(v.x), "=f"(v.y), "=f"(v.z), "=f"(v.w)
                             : "l"(src4 + j * 32));
                dst4[j * 32] = v;
            }
            __syncwarp();
        }

        unsigned long long acc[8];
#pragma unroll
        for (int j = 0; j < 8; j++) acc[j] = 0ull;

#pragma unroll
        for (int k = 0; k < 64; k++) {
            unsigned long long rp = pack2(Rreg[k]);
            const unsigned long long* hp = (const unsigned long long*)(hk + k * 16);
            ulonglong2 h01 = *(const ulonglong2*)(hp + 0);
            ulonglong2 h23 = *(const ulonglong2*)(hp + 2);
            ulonglong2 h45 = *(const ulonglong2*)(hp + 4);
            ulonglong2 h67 = *(const ulonglong2*)(hp + 6);
            fma2(acc[0], rp, h01.x); fma2(acc[1], rp, h01.y);
            fma2(acc[2], rp, h23.x); fma2(acc[3], rp, h23.y);
            fma2(acc[4], rp, h45.x); fma2(acc[5], rp, h45.y);
            fma2(acc[6], rp, h67.x); fma2(acc[7], rp, h67.y);
        }

        float* pprow = pprow0 + pbuf;
#pragma unroll
        for (int j = 0; j < 8; j++)
            *(unsigned long long*)(pprow + j * 2) = acc[j];
        __syncthreads();   // BAR_A: all partials (buffer t&1) ready

        // ---- merged reduce + pointwise + publish (warps 0-3) ----
        if (tid < 128) {
            float pre[4];
#pragma unroll
            for (int g4 = 0; g4 < 4; g4++) {
                float s = xpre[g4];
                const float* qp = sPart + pbuf + (g4 * 8 + pu) * 18 + pb;
#pragma unroll
                for (int k2 = 0; k2 < 16; k2++) s += qp[k2 * PS];
                pre[g4] = s;
            }
            float ez = __expf(2.f * pre[0]);
            float z = __fdividef(ez - 1.f, ez + 1.f);
            float o = __fdividef(1.f, 1.f + __expf(-pre[3]));
            float mn = fmaxf(pre[2] + mreg, pre[1]);
            float ip = __expf(pre[1] - mn);
            float fp = __expf(pre[2] + mreg - mn);
            creg = fp * creg + ip * z;
            nreg = fp * nreg + ip;
            mreg = mn;
            float h = o * __fdividef(creg, nreg);
            g_hbuf[t & 1][(u_base + pu) * 16 + pb] = h;
            if (write_a3) {
                // layer-1 GEMM operand: A3[m=t*16+b][Ah | Al | Ah]
                __nv_bfloat16 hh = __float2bfloat16(h);
                __nv_bfloat16 hl = __float2bfloat16(h - __bfloat162float(hh));
                __nv_bfloat16* a3 = g_A3 + ((size_t)t * 16 + pb) * 3072 + (u_base + pu);
                a3[0]    = hh;
                a3[2048] = hh;
                a3[1024] = hl;
            }
            asm volatile("bar.sync 1, 128;" ::: "memory");
            if (tid == 0) {
                __threadfence();
                g_flags[blockIdx.x * 8] = t + 1;
            }
        }
        // no BAR_B: sPart double-buffered; flag transitivity bounds skew
    }
}

// ===================================================================
// Final projection: h_last in g_hbuf[(T_STEPS-1)&1] = g_hbuf[1]
// ===================================================================
__global__ __launch_bounds__(256) void final_out(
    const float* __restrict__ Wout, const float* __restrict__ bout,
    float* __restrict__ out)
{
    const float* hsrc = g_hbuf[(T_STEPS - 1) & 1];
    int o = (blockIdx.x * blockDim.x + threadIdx.x) >> 5;
    int lane = threadIdx.x & 31;
    const float* wr = Wout + (size_t)o * 1024;
    float acc[16];
#pragma unroll
    for (int b = 0; b < 16; b++) acc[b] = 0.f;
    for (int k = lane; k < 1024; k += 32) {
        float w = wr[k];
        const float4* hp = (const float4*)(hsrc + k * 16);
        float4 h0 = hp[0], h1 = hp[1], h2 = hp[2], h3 = hp[3];
        acc[0]  += w * h0.x; acc[1]  += w * h0.y; acc[2]  += w * h0.z; acc[3]  += w * h0.w;
        acc[4]  += w * h1.x; acc[5]  += w * h1.y; acc[6]  += w * h1.z; acc[7]  += w * h1.w;
        acc[8]  += w * h2.x; acc[9]  += w * h2.y; acc[10] += w * h2.z; acc[11] += w * h2.w;
        acc[12] += w * h3.x; acc[13] += w * h3.y; acc[14] += w * h3.z; acc[15] += w * h3.w;
    }
#pragma unroll
    for (int b = 0; b < 16; b++) {
#pragma unroll
        for (int off = 16; off; off >>= 1)
            acc[b] += __shfl_down_sync(0xffffffffu, acc[b], off);
    }
    if (lane == 0) {
        float bo = bout[o];
#pragma unroll
        for (int b = 0; b < 16; b++)
            out[(size_t)b * 1024 + o] = acc[b] + bo;
    }
}

// ===================================================================
extern "C" void kernel_launch(void* const* d_in, const int* in_sizes, int n_in,
                              void* d_out, int out_size)
{
    const float* x    = (const float*)d_in[0];
    const float* W    = (const float*)d_in[1];
    const float* R    = (const float*)d_in[2];
    const float* bias = (const float*)d_in[3];
    const float* Wout = (const float*)d_in[4];
    const float* bout = (const float*)d_in[5];
    float* out = (float*)d_out;

    const int REC_SMEM = (16384 + 2 * 16 * PS + 64) * 4;   // 140,544 B
    cudaFuncSetAttribute(slstm_rec, cudaFuncAttributeMaxDynamicSharedMemorySize, REC_SMEM);
    const int GEMM_SMEM = 8 * TILE_B;                       // 81,920 B
    cudaFuncSetAttribute(hmma_gemm, cudaFuncAttributeMaxDynamicSharedMemorySize, GEMM_SMEM);

    __nv_bfloat16 *ga3, *gw3;
    cudaGetSymbolAddress((void**)&ga3, g_A3);
    cudaGetSymbolAddress((void**)&gw3, g_W3);

    dim3 tgrid(32, 128);
    // ---- layer 0 ----
    split3<<<4096, 256>>>(W, gw3, 1024, 2048, 0);            // W0 -> Wh|Wh|Wl
    split3<<<16384, 256>>>(x, ga3, 2048, 1024, 1);           // x  -> Ah|Al|Ah
    hmma_gemm<<<tgrid, 256, GEMM_SMEM>>>(bias, 0);
    slstm_rec<<<NCTA, 512, REC_SMEM>>>(R, 1);                // writes A3 for layer 1
    // ---- layer 1 ----
    split3<<<4096, 256>>>(W + (size_t)4096 * 1024, gw3, 1024, 2048, 0);
    hmma_gemm<<<tgrid, 256, GEMM_SMEM>>>(bias, 4096);
    slstm_rec<<<NCTA, 512, REC_SMEM>>>(R + (size_t)4096 * 1024, 0);
    // ---- output ----
    final_out<<<128, 256>>>(Wout, bout, out);
}

// round 17
// speedup vs baseline: 1.1409x; 1.0592x over previous
#include <cuda_runtime.h>
#include <cuda_bf16.h>
#include <math.h>
#include <stdint.h>

#define T_STEPS 1024
#define NCTA 128
#define PS 584   // sPart per-ksplit stride (floats)

// -------- packed fp32x2 helpers --------
__device__ __forceinline__ unsigned long long pack2(float x) {
    unsigned long long r; asm("mov.b64 %0, {%1, %1};" : "=l"(r) : "f"(x)); return r;
}
__device__ __forceinline__ void fma2(unsigned long long &d, unsigned long long a, unsigned long long b) {
    asm("fma.rn.f32x2 %0, %1, %2, %0;" : "+l"(d) : "l"(a), "l"(b));
}

// -------- scratch (static device globals) --------
__device__ float g_xproj[(size_t)16384 * 4096];       // 256 MB
__device__ float g_hs[(size_t)16 * 1024 * 1024];      // 64 MB [b][t][h]
__device__ float g_hbuf[2][16384];                    // h double buffer [k][b]
__device__ int   g_flags[NCTA * 8];
__device__ unsigned int g_bar_count;
__device__ volatile unsigned int g_bar_gen;
__device__ __nv_bfloat16 g_A3[(size_t)16384 * 3072];  // 96 MB
__device__ __nv_bfloat16 g_W3[(size_t)4096 * 3072];   // 24 MB

// -------- software grid barrier (init only; replay-safe) --------
__device__ __forceinline__ void grid_barrier() {
    __syncthreads();
    if (threadIdx.x == 0) {
        __threadfence();
        unsigned int gen = g_bar_gen;
        unsigned int t = atomicAdd(&g_bar_count, 1u);
        if (t == NCTA - 1) {
            g_bar_count = 0u;
            __threadfence();
            g_bar_gen = gen + 1u;
        } else {
            while (g_bar_gen == gen) { }
            __threadfence();
        }
    }
    __syncthreads();
}

// -------- cp.async helpers --------
__device__ __forceinline__ uint32_t smem_u32(const void* p) {
    uint32_t a;
    asm("{ .reg .u64 t; cvta.to.shared.u64 t, %1; cvt.u32.u64 %0, t; }" : "=r"(a) : "l"(p));
    return a;
}
__device__ __forceinline__ void cp16(uint32_t dst, const void* src) {
    asm volatile("cp.async.cg.shared.global [%0], [%1], 16;" :: "r"(dst), "l"(src));
}
__device__ __forceinline__ void cp_commit() { asm volatile("cp.async.commit_group;"); }
template <int N>
__device__ __forceinline__ void cp_wait() { asm volatile("cp.async.wait_group %0;" :: "n"(N)); }

// -------- mma.sync bf16 --------
__device__ __forceinline__ void mma_bf16(float* c, const uint32_t* a, uint32_t b0, uint32_t b1) {
    asm volatile(
        "mma.sync.aligned.m16n8k16.row.col.f32.bf16.bf16.f32 "
        "{%0,%1,%2,%3}, {%4,%5,%6,%7}, {%8,%9}, {%0,%1,%2,%3};"
        : "+f"(c[0]), "+f"(c[1]), "+f"(c[2]), "+f"(c[3])
        : "r"(a[0]), "r"(a[1]), "r"(a[2]), "r"(a[3]), "r"(b0), "r"(b1));
}

// ===================================================================
// split3: fp32 [M][1024] -> bf16 [M][3072] split-concat (xproj prep)
// ===================================================================
__global__ __launch_bounds__(256) void split3(
    const float* __restrict__ src, __nv_bfloat16* __restrict__ dst,
    int off2, int off3, int seq_layout)
{
    size_t m = blockIdx.x;
    int k = threadIdx.x * 4;
    size_t si = seq_layout ? ((size_t)(m & 15) * 1048576 + (size_t)(m >> 4) * 1024 + k)
                           : (m * 1024 + k);
    float4 v = *(const float4*)(src + si);
    __nv_bfloat16 h0 = __float2bfloat16(v.x), h1 = __float2bfloat16(v.y);
    __nv_bfloat16 h2 = __float2bfloat16(v.z), h3 = __float2bfloat16(v.w);
    __nv_bfloat162 H0 = __halves2bfloat162(h0, h1), H1 = __halves2bfloat162(h2, h3);
    __nv_bfloat162 L0 = __halves2bfloat162(__float2bfloat16(v.x - __bfloat162float(h0)),
                                           __float2bfloat16(v.y - __bfloat162float(h1)));
    __nv_bfloat162 L1 = __halves2bfloat162(__float2bfloat16(v.z - __bfloat162float(h2)),
                                           __float2bfloat16(v.w - __bfloat162float(h3)));
    __nv_bfloat16* base = dst + m * 3072;
    *(__nv_bfloat162*)(base + k) = H0;          *(__nv_bfloat162*)(base + k + 2) = H1;
    *(__nv_bfloat162*)(base + off2 + k) = H0;   *(__nv_bfloat162*)(base + off2 + k + 2) = H1;
    *(__nv_bfloat162*)(base + off3 + k) = L0;   *(__nv_bfloat162*)(base + off3 + k + 2) = L1;
}

// ===================================================================
// Phase A HMMA GEMM, 4-stage cp.async pipeline (R11, known good)
// ===================================================================
#define BK 32
#define KIT 96
#define TILE_B 10240
__global__ __launch_bounds__(256, 2) void hmma_gemm(const float* __restrict__ bias, int bias_off)
{
    extern __shared__ __align__(16) char gsm[];
    __nv_bfloat16* As = (__nv_bfloat16*)gsm;
    __nv_bfloat16* Bs = (__nv_bfloat16*)(gsm + 4 * TILE_B);

    int tid = threadIdx.x;
    int n0 = blockIdx.x * 128, m0 = blockIdx.y * 128;
    int warp = tid >> 5, lane = tid & 31;
    int wm = (warp & 1) * 64, wn = (warp >> 1) * 32;
    int g = lane >> 2, q = lane & 3;

    int srow = tid >> 1;
    int scol = (tid & 1) * 16;
    const __nv_bfloat16* gA = g_A3 + (size_t)(m0 + srow) * 3072 + scol;
    const __nv_bfloat16* gB = g_W3 + (size_t)(n0 + srow) * 3072 + scol;
    uint32_t sOff = (srow * 40 + scol) * 2;
    uint32_t aBase = smem_u32(As), bBase = smem_u32(Bs);

    float acc[4][4][4];
#pragma unroll
    for (int i = 0; i < 4; i++)
#pragma unroll
        for (int j = 0; j < 4; j++)
#pragma unroll
            for (int r = 0; r < 4; r++) acc[i][j][r] = 0.f;

#pragma unroll
    for (int s = 0; s < 3; s++) {
        const __nv_bfloat16* a = gA + s * BK;
        const __nv_bfloat16* b = gB + s * BK;
        cp16(aBase + s * TILE_B + sOff, a);  cp16(aBase + s * TILE_B + sOff + 16, a + 8);
        cp16(bBase + s * TILE_B + sOff, b);  cp16(bBase + s * TILE_B + sOff + 16, b + 8);
        cp_commit();
    }

    for (int c = 0; c < KIT; c++) {
        cp_wait<2>();
        __syncthreads();

        if (c + 3 < KIT) {
            int s = (c + 3) & 3;
            const __nv_bfloat16* a = gA + (c + 3) * BK;
            const __nv_bfloat16* b = gB + (c + 3) * BK;
            cp16(aBase + s * TILE_B + sOff, a);  cp16(aBase + s * TILE_B + sOff + 16, a + 8);
            cp16(bBase + s * TILE_B + sOff, b);  cp16(bBase + s * TILE_B + sOff + 16, b + 8);
        }
        cp_commit();

        const __nv_bfloat16* Ab = As + (c & 3) * (TILE_B / 2);
        const __nv_bfloat16* Bb = Bs + (c & 3) * (TILE_B / 2);
#pragma unroll
        for (int kk = 0; kk < 32; kk += 16) {
            uint32_t af[4][4];
#pragma unroll
            for (int i = 0; i < 4; i++) {
                const __nv_bfloat16* p = Ab + (wm + i * 16 + g) * 40 + kk + 2 * q;
                af[i][0] = *(const uint32_t*)p;
                af[i][1] = *(const uint32_t*)(p + 8 * 40);
                af[i][2] = *(const uint32_t*)(p + 8);
                af[i][3] = *(const uint32_t*)(p + 8 * 40 + 8);
            }
#pragma unroll
            for (int j = 0; j < 4; j++) {
                const __nv_bfloat16* p = Bb + (wn + j * 8 + g) * 40 + kk + 2 * q;
                uint32_t b0 = *(const uint32_t*)p;
                uint32_t b1 = *(const uint32_t*)(p + 8);
#pragma unroll
                for (int i = 0; i < 4; i++)
                    mma_bf16(acc[i][j], af[i], b0, b1);
            }
        }
    }

#pragma unroll
    for (int j = 0; j < 4; j++) {
        int n = n0 + wn + j * 8 + 2 * q;
        float b0 = __ldg(bias + bias_off + n);
        float b1 = __ldg(bias + bias_off + n + 1);
#pragma unroll
        for (int i = 0; i < 4; i++) {
            int m = m0 + wm + i * 16 + g;
            float2 v0 = { acc[i][j][0] + b0, acc[i][j][1] + b1 };
            float2 v1 = { acc[i][j][2] + b0, acc[i][j][3] + b1 };
            *(float2*)(g_xproj + (size_t)m * 4096 + n) = v0;
            *(float2*)(g_xproj + (size_t)(m + 8) * 4096 + n) = v1;
        }
    }
}

// ===================================================================
// Phase B: persistent sLSTM recurrence — R11 core with Rreg 48/16
// hybrid: 48 k in registers, 16 k in SMEM (transposed, conflict-free
// lane-distinct LDS.32). Frees ~18 regs so ptxas can software-
// pipeline the broadcast h LDS.128 loads across k-iterations.
// 512 threads; warp = 64-k split; lane = gate row; double-buffered
// partials (no BAR_B); merged reduce+pointwise; ld.acquire polling.
// SMEM: sR 32K + sH 64K + sPart 2*16*PS*4 = 173.25 KB (1 CTA/SM).
// ===================================================================
__global__ __launch_bounds__(512, 1) void slstm_rec(const float* __restrict__ Rl)
{
    extern __shared__ float smem[];
    float* sR    = smem;                 // [16 warps][16 k][32 lanes]
    float* sH    = smem + 8192;          // [1024][16]
    float* sPart = smem + 24576;         // [2][16][PS]

    int tid = threadIdx.x;
    int ks = tid >> 5;
    int lane = tid & 31;
    int u_base = blockIdx.x * 8;

    if (tid == 0) g_flags[blockIdx.x * 8] = 0;
    grid_barrier();

    int grow = (lane >> 3) * 1024 + u_base + (lane & 7);
    const float* rrow = Rl + (size_t)grow * 1024 + ks * 64;
    // first 48 k -> registers
    float Rreg[48];
#pragma unroll
    for (int j = 0; j < 48; j += 4) {
        float4 v = *(const float4*)(rrow + j);
        Rreg[j] = v.x; Rreg[j + 1] = v.y; Rreg[j + 2] = v.z; Rreg[j + 3] = v.w;
    }
    // last 16 k -> smem transposed: sR[(ks*16 + kk)*32 + lane]
#pragma unroll
    for (int j = 0; j < 16; j += 4) {
        float4 v = *(const float4*)(rrow + 48 + j);
        sR[(ks * 16 + j + 0) * 32 + lane] = v.x;
        sR[(ks * 16 + j + 1) * 32 + lane] = v.y;
        sR[(ks * 16 + j + 2) * 32 + lane] = v.z;
        sR[(ks * 16 + j + 3) * 32 + lane] = v.w;
    }

    for (int i = tid; i < 16384; i += 512) sH[i] = 0.f;
    __syncthreads();

    // pointwise mapping (tid < 128): b = tid&15, u = tid>>4
    int pb = tid & 15, pu = tid >> 4;
    float creg = 0.f, nreg = 1.f, mreg = 0.f;

    const float* hk = sH + ks * 1024;
    const float* rs = sR + ks * 16 * 32 + lane;
    float* pprow0 = sPart + ks * PS + lane * 18;
    const int* myflag = g_flags + (8 * ks + (lane & 7)) * 8;

    for (int t = 0; t < T_STEPS; t++) {
        int pbuf = (t & 1) * (16 * PS);

        float xpre[4];
        if (tid < 128) {
            const float* xp = g_xproj + ((size_t)t * 16 + pb) * 4096 + u_base + pu;
            xpre[0] = __ldg(xp);
            xpre[1] = __ldg(xp + 1024);
            xpre[2] = __ldg(xp + 2048);
            xpre[3] = __ldg(xp + 3072);
        }

        if (t > 0) {
            for (;;) {
                int f;
                asm volatile("ld.acquire.gpu.global.b32 %0, [%1];" : "=r"(f) : "l"(myflag));
                if (__all_sync(0xffffffffu, f >= t)) break;
            }
            const float4* src4 = (const float4*)(g_hbuf[(t - 1) & 1]) + ks * 256 + lane;
            float4* dst4 = (float4*)sH + ks * 256 + lane;
#pragma unroll
            for (int j = 0; j < 8; j++) {
                float4 v;
                asm volatile("ld.global.cg.v4.f32 {%0,%1,%2,%3}, [%4];"
                             : "=f"(v.x), "=f"(v.y), "=f"(v.z), "=f"(v.w)
                             : "l"(src4 + j * 32));
                dst4[j * 32] = v;
            }
            __syncwarp();
        }

        unsigned long long acc[8];
#pragma unroll
        for (int j = 0; j < 8; j++) acc[j] = 0ull;

        // k 0..47: R from registers
#pragma unroll
        for (int k = 0; k < 48; k++) {
            unsigned long long rp = pack2(Rreg[k]);
            const unsigned long long* hp = (const unsigned long long*)(hk + k * 16);
            ulonglong2 h01 = *(const ulonglong2*)(hp + 0);
            ulonglong2 h23 = *(const ulonglong2*)(hp + 2);
            ulonglong2 h45 = *(const ulonglong2*)(hp + 4);
            ulonglong2 h67 = *(const ulonglong2*)(hp + 6);
            fma2(acc[0], rp, h01.x); fma2(acc[1], rp, h01.y);
            fma2(acc[2], rp, h23.x); fma2(acc[3], rp, h23.y);
            fma2(acc[4], rp, h45.x); fma2(acc[5], rp, h45.y);
            fma2(acc[6], rp, h67.x); fma2(acc[7], rp, h67.y);
        }
        // k 48..63: R from smem (lane-distinct LDS.32, conflict-free)
#pragma unroll
        for (int k = 0; k < 16; k++) {
            unsigned long long rp = pack2(rs[k * 32]);
            const unsigned long long* hp = (const unsigned long long*)(hk + (48 + k) * 16);
            ulonglong2 h01 = *(const ulonglong2*)(hp + 0);
            ulonglong2 h23 = *(const ulonglong2*)(hp + 2);
            ulonglong2 h45 = *(const ulonglong2*)(hp + 4);
            ulonglong2 h67 = *(const ulonglong2*)(hp + 6);
            fma2(acc[0], rp, h01.x); fma2(acc[1], rp, h01.y);
            fma2(acc[2], rp, h23.x); fma2(acc[3], rp, h23.y);
            fma2(acc[4], rp, h45.x); fma2(acc[5], rp, h45.y);
            fma2(acc[6], rp, h67.x); fma2(acc[7], rp, h67.y);
        }

        float* pprow = pprow0 + pbuf;
#pragma unroll
        for (int j = 0; j < 8; j++)
            *(unsigned long long*)(pprow + j * 2) = acc[j];
        __syncthreads();   // BAR_A: all partials (buffer t&1) ready

        // ---- merged reduce + pointwise + publish (warps 0-3) ----
        if (tid < 128) {
            float pre[4];
#pragma unroll
            for (int g4 = 0; g4 < 4; g4++) {
                float s = xpre[g4];
                const float* qp = sPart + pbuf + (g4 * 8 + pu) * 18 + pb;
#pragma unroll
                for (int k2 = 0; k2 < 16; k2++) s += qp[k2 * PS];
                pre[g4] = s;
            }
            float ez = __expf(2.f * pre[0]);
            float z = __fdividef(ez - 1.f, ez + 1.f);
            float o = __fdividef(1.f, 1.f + __expf(-pre[3]));
            float mn = fmaxf(pre[2] + mreg, pre[1]);
            float ip = __expf(pre[1] - mn);
            float fp = __expf(pre[2] + mreg - mn);
            creg = fp * creg + ip * z;
            nreg = fp * nreg + ip;
            mreg = mn;
            float h = o * __fdividef(creg, nreg);
            g_hbuf[t & 1][(u_base + pu) * 16 + pb] = h;
            g_hs[(size_t)pb * 1048576 + (size_t)t * 1024 + u_base + pu] = h;
            asm volatile("bar.sync 1, 128;" ::: "memory");
            if (tid == 0) {
                __threadfence();
                g_flags[blockIdx.x * 8] = t + 1;
            }
        }
        // no BAR_B: sPart double-buffered; flag transitivity bounds skew
    }
}

// ===================================================================
// Final projection: h_last in g_hbuf[(T_STEPS-1)&1] = g_hbuf[1]
// ===================================================================
__global__ __launch_bounds__(256) void final_out(
    const float* __restrict__ Wout, const float* __restrict__ bout,
    float* __restrict__ out)
{
    const float* hsrc = g_hbuf[(T_STEPS - 1) & 1];
    int o = (blockIdx.x * blockDim.x + threadIdx.x) >> 5;
    int lane = threadIdx.x & 31;
    const float* wr = Wout + (size_t)o * 1024;
    float acc[16];
#pragma unroll
    for (int b = 0; b < 16; b++) acc[b] = 0.f;
    for (int k = lane; k < 1024; k += 32) {
        float w = wr[k];
        const float4* hp = (const float4*)(hsrc + k * 16);
        float4 h0 = hp[0], h1 = hp[1], h2 = hp[2], h3 = hp[3];
        acc[0]  += w * h0.x; acc[1]  += w * h0.y; acc[2]  += w * h0.z; acc[3]  += w * h0.w;
        acc[4]  += w * h1.x; acc[5]  += w * h1.y; acc[6]  += w * h1.z; acc[7]  += w * h1.w;
        acc[8]  += w * h2.x; acc[9]  += w * h2.y; acc[10] += w * h2.z; acc[11] += w * h2.w;
        acc[12] += w * h3.x; acc[13] += w * h3.y; acc[14] += w * h3.z; acc[15] += w * h3.w;
    }
#pragma unroll
    for (int b = 0; b < 16; b++) {
#pragma unroll
        for (int off = 16; off; off >>= 1)
            acc[b] += __shfl_down_sync(0xffffffffu, acc[b], off);
    }
    if (lane == 0) {
        float bo = bout[o];
#pragma unroll
        for (int b = 0; b < 16; b++)
            out[(size_t)b * 1024 + o] = acc[b] + bo;
    }
}

// ===================================================================
extern "C" void kernel_launch(void* const* d_in, const int* in_sizes, int n_in,
                              void* d_out, int out_size)
{
    const float* x    = (const float*)d_in[0];
    const float* W    = (const float*)d_in[1];
    const float* R    = (const float*)d_in[2];
    const float* bias = (const float*)d_in[3];
    const float* Wout = (const float*)d_in[4];
    const float* bout = (const float*)d_in[5];
    float* out = (float*)d_out;

    const int REC_SMEM = (8192 + 16384 + 2 * 16 * PS + 64) * 4;   // 173,312 B
    cudaFuncSetAttribute(slstm_rec, cudaFuncAttributeMaxDynamicSharedMemorySize, REC_SMEM);
    const int GEMM_SMEM = 8 * TILE_B;                              // 81,920 B
    cudaFuncSetAttribute(hmma_gemm, cudaFuncAttributeMaxDynamicSharedMemorySize, GEMM_SMEM);

    __nv_bfloat16 *ga3, *gw3;
    float *ghs;
    cudaGetSymbolAddress((void**)&ga3, g_A3);
    cudaGetSymbolAddress((void**)&gw3, g_W3);
    cudaGetSymbolAddress((void**)&ghs, g_hs);

    dim3 tgrid(32, 128);
    // ---- layer 0 ----
    split3<<<4096, 256>>>(W, gw3, 1024, 2048, 0);
    split3<<<16384, 256>>>(x, ga3, 2048, 1024, 1);
    hmma_gemm<<<tgrid, 256, GEMM_SMEM>>>(bias, 0);
    slstm_rec<<<NCTA, 512, REC_SMEM>>>(R);
    // ---- layer 1 ----
    split3<<<4096, 256>>>(W + (size_t)4096 * 1024, gw3, 1024, 2048, 0);
    split3<<<16384, 256>>>(ghs, ga3, 2048, 1024, 1);
    hmma_gemm<<<tgrid, 256, GEMM_SMEM>>>(bias, 4096);
    slstm_rec<<<NCTA, 512, REC_SMEM>>>(R + (size_t)4096 * 1024);
    // ---- output ----
    final_out<<<128, 256>>>(Wout, bout, out);
}